// round 1
// baseline (speedup 1.0000x reference)
#include <cuda_runtime.h>

// FiniteDifference: x [B=4, T=16, H=128, W=128, C=16] fp32
// out = concat(dy (d/dH), dx (d/dW), dz (d/dT)), each same shape as x.
// Central difference with zero padding: out[i] = x[i+1] - x[i-1].
//
// Strategy: one thread per float4 (C=16 -> 4 float4 per pixel).
// Linear float4 index i decodes as:
//   c4 = i & 3        (which float4 within channel dim)
//   w  = (i >> 2)  & 127
//   h  = (i >> 9)  & 127
//   t  = (i >> 16) & 15
//   b  =  i >> 20
// Neighbor strides in float4 units: W: +-4, H: +-512, T: +-65536.

#define N4_TOTAL (4 * 16 * 128 * 128 * 4)  // 4,194,304 float4 elements

__global__ void __launch_bounds__(256)
fd_kernel(const float4* __restrict__ x, float4* __restrict__ out)
{
    int i = blockIdx.x * blockDim.x + threadIdx.x;
    // grid sized exactly; no bounds check needed (N4_TOTAL % 256 == 0)

    int w = (i >> 2)  & 127;
    int h = (i >> 9)  & 127;
    int t = (i >> 16) & 15;

    const float4 zero = make_float4(0.f, 0.f, 0.f, 0.f);

    float4 hp = (h < 127) ? x[i + 512]   : zero;
    float4 hm = (h > 0)   ? x[i - 512]   : zero;
    float4 wp = (w < 127) ? x[i + 4]     : zero;
    float4 wm = (w > 0)   ? x[i - 4]     : zero;
    float4 tp = (t < 15)  ? x[i + 65536] : zero;
    float4 tm = (t > 0)   ? x[i - 65536] : zero;

    float4 dy, dx, dz;
    dy.x = hp.x - hm.x; dy.y = hp.y - hm.y; dy.z = hp.z - hm.z; dy.w = hp.w - hm.w;
    dx.x = wp.x - wm.x; dx.y = wp.y - wm.y; dx.z = wp.z - wm.z; dx.w = wp.w - wm.w;
    dz.x = tp.x - tm.x; dz.y = tp.y - tm.y; dz.z = tp.z - tm.z; dz.w = tp.w - tm.w;

    out[i]                = dy;
    out[i + N4_TOTAL]     = dx;
    out[i + 2 * N4_TOTAL] = dz;
}

extern "C" void kernel_launch(void* const* d_in, const int* in_sizes, int n_in,
                              void* d_out, int out_size)
{
    const float4* x = (const float4*)d_in[0];
    float4* out = (float4*)d_out;

    const int threads = 256;
    const int blocks = N4_TOTAL / threads;  // 16384
    fd_kernel<<<blocks, threads>>>(x, out);
}